// round 2
// baseline (speedup 1.0000x reference)
#include <cuda_runtime.h>
#include <cuda_bf16.h>
#include <mma.h>

using namespace nvcuda;
typedef __nv_bfloat16 bf16;

#define B_   2
#define S_   2048
#define D_   1024
#define H_   16
#define DK_  64
#define DFF_ 4096
#define T_   (B_*S_)    // 4096 tokens
#define BH_  (B_*H_)    // 32 batched heads

// ---------------- scratch (device globals; no allocation allowed) ----------------
__device__ bf16  g_wqkv[D_*3*D_];
__device__ bf16  g_wo  [D_*D_];
__device__ bf16  g_xn  [T_*D_];
__device__ bf16  g_qkv [T_*3*D_];
__device__ bf16  g_q   [BH_*S_*DK_];
__device__ bf16  g_kT  [BH_*DK_*S_];
__device__ bf16  g_v   [BH_*S_*DK_];
__device__ float g_scores[(size_t)BH_*S_*S_];   // 536 MB
__device__ bf16  g_attn  [(size_t)BH_*S_*S_];   // 268 MB
__device__ bf16  g_ctx [BH_*S_*DK_];
__device__ bf16  g_ctxr[T_*D_];
__device__ float g_xnf [T_*D_];                 // fp32 LN2 output
__device__ float g_ff1f[(size_t)T_*DFF_];       // fp32 FFN hidden (64 MB)

// ---------------- small utility kernels ----------------
__global__ void eb_cast_kernel(const float4* __restrict__ src, __nv_bfloat162* __restrict__ dst, int n4) {
    int i = blockIdx.x * blockDim.x + threadIdx.x;
    if (i < n4) {
        float4 v = src[i];
        dst[2*i]   = __floats2bfloat162_rn(v.x, v.y);
        dst[2*i+1] = __floats2bfloat162_rn(v.z, v.w);
    }
}

__global__ void eb_pack_wqkv(const float* __restrict__ wq, const float* __restrict__ wk,
                             const float* __restrict__ wv) {
    int i = blockIdx.x * 256 + threadIdx.x;
    if (i >= D_*3*D_) return;
    int k = i / (3*D_), n = i % (3*D_);
    const float* src = (n < D_) ? wq : ((n < 2*D_) ? wk : wv);
    g_wqkv[i] = __float2bfloat16(src[k*D_ + (n & (D_-1))]);
}

__global__ void eb_reshape_qkv() {
    int i = blockIdx.x * 256 + threadIdx.x;
    if (i >= T_*3*D_) return;
    int t = i / (3*D_), n = i % (3*D_);
    int b = t / S_, s = t % S_;
    int sel = n / D_, d = n % D_;
    int h = d / DK_, dk = d % DK_;
    int bh = b*H_ + h;
    bf16 val = g_qkv[i];
    if (sel == 0)      g_q [((size_t)bh*S_  + s )*DK_ + dk] = val;
    else if (sel == 1) g_kT[((size_t)bh*DK_ + dk)*S_  + s ] = val;
    else               g_v [((size_t)bh*S_  + s )*DK_ + dk] = val;
}

__global__ void eb_reshape_ctx() {
    int i = blockIdx.x * 256 + threadIdx.x;
    if (i >= T_*D_) return;
    int t = i / D_, d = i % D_;
    int b = t / S_, s = t % S_;
    int h = d / DK_, dk = d % DK_;
    g_ctxr[i] = g_ctx[(((size_t)(b*H_ + h))*S_ + s)*DK_ + dk];
}

// ---------------- LayerNorm (TF-style: eps added to std) ----------------
template<typename OT>
__global__ void eb_ln_kernel(const float* __restrict__ x, const float* __restrict__ ga,
                             const float* __restrict__ gb, OT* __restrict__ out) {
    __shared__ float red[2][8];
    int row = blockIdx.x, tid = threadIdx.x;       // 256 threads, D=1024 -> 1 float4/thread
    const float4* xr = (const float4*)(x + (size_t)row * D_);
    float4 v = xr[tid];
    float s = v.x + v.y + v.z + v.w;
    #pragma unroll
    for (int o = 16; o; o >>= 1) s += __shfl_xor_sync(0xffffffffu, s, o);
    if ((tid & 31) == 0) red[0][tid >> 5] = s;
    __syncthreads();
    float mean = 0.f;
    #pragma unroll
    for (int i = 0; i < 8; i++) mean += red[0][i];
    mean *= (1.0f / D_);
    float d0 = v.x - mean, d1 = v.y - mean, d2 = v.z - mean, d3 = v.w - mean;
    float q = d0*d0 + d1*d1 + d2*d2 + d3*d3;
    #pragma unroll
    for (int o = 16; o; o >>= 1) q += __shfl_xor_sync(0xffffffffu, q, o);
    if ((tid & 31) == 0) red[1][tid >> 5] = q;
    __syncthreads();
    float var = 0.f;
    #pragma unroll
    for (int i = 0; i < 8; i++) var += red[1][i];
    var *= (1.0f / D_);
    float inv = 1.f / (sqrtf(var) + 1e-6f);
    int c = tid * 4;
    float4 a4 = *(const float4*)(ga + c);
    float4 b4 = *(const float4*)(gb + c);
    float o0 = a4.x * d0 * inv + b4.x;
    float o1 = a4.y * d1 * inv + b4.y;
    float o2 = a4.z * d2 * inv + b4.z;
    float o3 = a4.w * d3 * inv + b4.w;
    if constexpr (sizeof(OT) == 2) {
        __nv_bfloat162* op = (__nv_bfloat162*)((bf16*)out + (size_t)row * D_ + c);
        op[0] = __floats2bfloat162_rn(o0, o1);
        op[1] = __floats2bfloat162_rn(o2, o3);
    } else {
        float4* op = (float4*)((float*)out + (size_t)row * D_ + c);
        *op = make_float4(o0, o1, o2, o3);
    }
}

// ---------------- row softmax over S=2048 (256 threads, 8 elems/thread) ----------------
__global__ void eb_softmax_kernel() {
    __shared__ float red[2][8];
    size_t row = blockIdx.x;                       // B*H*S = 65536 rows
    int tid = threadIdx.x;
    const float4* p = (const float4*)(g_scores + row * S_);
    float4 a = p[tid], b = p[tid + 256];
    float m = fmaxf(fmaxf(fmaxf(a.x, a.y), fmaxf(a.z, a.w)),
                    fmaxf(fmaxf(b.x, b.y), fmaxf(b.z, b.w)));
    #pragma unroll
    for (int o = 16; o; o >>= 1) m = fmaxf(m, __shfl_xor_sync(0xffffffffu, m, o));
    if ((tid & 31) == 0) red[0][tid >> 5] = m;
    __syncthreads();
    float gm = -1e30f;
    #pragma unroll
    for (int i = 0; i < 8; i++) gm = fmaxf(gm, red[0][i]);
    float e0 = __expf(a.x - gm), e1 = __expf(a.y - gm), e2 = __expf(a.z - gm), e3 = __expf(a.w - gm);
    float e4 = __expf(b.x - gm), e5 = __expf(b.y - gm), e6 = __expf(b.z - gm), e7 = __expf(b.w - gm);
    float s = e0 + e1 + e2 + e3 + e4 + e5 + e6 + e7;
    #pragma unroll
    for (int o = 16; o; o >>= 1) s += __shfl_xor_sync(0xffffffffu, s, o);
    if ((tid & 31) == 0) red[1][tid >> 5] = s;
    __syncthreads();
    float tot = 0.f;
    #pragma unroll
    for (int i = 0; i < 8; i++) tot += red[1][i];
    float inv = 1.f / tot;
    __nv_bfloat162* o = (__nv_bfloat162*)(g_attn + row * S_);
    o[tid*2]         = __floats2bfloat162_rn(e0 * inv, e1 * inv);
    o[tid*2 + 1]     = __floats2bfloat162_rn(e2 * inv, e3 * inv);
    o[512 + tid*2]   = __floats2bfloat162_rn(e4 * inv, e5 * inv);
    o[512 + tid*2+1] = __floats2bfloat162_rn(e6 * inv, e7 * inv);
}

// ---------------- generic batched bf16 wmma GEMM, fp32 accum ----------------
// C[M,N] = A[M,K] @ B[K,N], row-major, batched via blockIdx.z with element strides.
// EPI: 0 = store bf16 | 2 = +residual, store f32 | 3 = *scale, mask(-1e9), store f32
template<int BN, int EPI>
__global__ void __launch_bounds__(256) eb_gemm_kernel(
    const bf16* __restrict__ A, size_t sA, int lda,
    const bf16* __restrict__ Bm, size_t sB, int ldb,
    void* __restrict__ Cout, size_t sC, int ldc,
    const float* __restrict__ resid,
    const int* __restrict__ mask,
    int K, float scale)
{
    constexpr int BM = 128, BK = 32;
    constexpr int WARPS_N = BN / 32;          // 4 (BN=128) or 2 (BN=64)
    constexpr int WARPS_M = 8 / WARPS_N;      // 2 or 4
    constexpr int WM = BM / WARPS_M;          // 64 or 32
    constexpr int FM = WM / 16;               // 4 or 2

    __shared__ bf16  As[BM][BK + 8];
    __shared__ bf16  Bs[BK][BN + 8];
    __shared__ float epi[8][16 * 20];

    int z = blockIdx.z;
    A  += (size_t)z * sA;
    Bm += (size_t)z * sB;
    int m0 = blockIdx.y * BM;
    int n0 = blockIdx.x * BN;
    int tid = threadIdx.x;
    int w = tid >> 5, lane = tid & 31;
    int wm = w / WARPS_N, wn = w % WARPS_N;

    wmma::fragment<wmma::accumulator, 16, 16, 16, float> acc[FM][2];
    #pragma unroll
    for (int i = 0; i < FM; i++)
        #pragma unroll
        for (int j = 0; j < 2; j++) wmma::fill_fragment(acc[i][j], 0.f);

    for (int k0 = 0; k0 < K; k0 += BK) {
        #pragma unroll
        for (int i = 0; i < 2; i++) {
            int vi = tid + i * 256;
            int r = vi >> 2, c = (vi & 3) * 8;
            *(uint4*)&As[r][c] = *(const uint4*)&A[(size_t)(m0 + r) * lda + k0 + c];
        }
        constexpr int BNV = BN / 8;
        constexpr int NBV = BK * BNV;
        #pragma unroll
        for (int i = 0; i < NBV / 256; i++) {
            int vi = tid + i * 256;
            int r = vi / BNV, c = (vi % BNV) * 8;
            *(uint4*)&Bs[r][c] = *(const uint4*)&Bm[(size_t)(k0 + r) * ldb + n0 + c];
        }
        __syncthreads();
        #pragma unroll
        for (int kk = 0; kk < BK; kk += 16) {
            wmma::fragment<wmma::matrix_a, 16, 16, 16, bf16, wmma::row_major> af[FM];
            wmma::fragment<wmma::matrix_b, 16, 16, 16, bf16, wmma::row_major> bfr[2];
            #pragma unroll
            for (int i = 0; i < FM; i++)
                wmma::load_matrix_sync(af[i], &As[wm * WM + i * 16][kk], BK + 8);
            #pragma unroll
            for (int j = 0; j < 2; j++)
                wmma::load_matrix_sync(bfr[j], &Bs[kk][wn * 32 + j * 16], BN + 8);
            #pragma unroll
            for (int i = 0; i < FM; i++)
                #pragma unroll
                for (int j = 0; j < 2; j++)
                    wmma::mma_sync(acc[i][j], af[i], bfr[j], acc[i][j]);
        }
        __syncthreads();
    }

    float* Cf = (float*)Cout;
    bf16*  Cb = (bf16*)Cout;
    size_t cbase = (size_t)z * sC;
    #pragma unroll
    for (int i = 0; i < FM; i++) {
        #pragma unroll
        for (int j = 0; j < 2; j++) {
            wmma::store_matrix_sync(&epi[w][0], acc[i][j], 20, wmma::mem_row_major);
            __syncwarp();
            int gr0 = m0 + wm * WM + i * 16;
            int gc0 = n0 + wn * 32 + j * 16;
            #pragma unroll
            for (int e = 0; e < 8; e++) {
                int ei = lane + e * 32;
                int rr = ei >> 4, cc = ei & 15;
                float v2 = epi[w][rr * 20 + cc];
                int gr = gr0 + rr, gc = gc0 + cc;
                size_t off = cbase + (size_t)gr * ldc + gc;
                if (EPI == 0) {
                    Cb[off] = __float2bfloat16(v2);
                } else if (EPI == 2) {
                    Cf[off] = v2 + resid[off];
                } else {
                    v2 *= scale;
                    if (mask[(z >> 4) * S_ + gc] == 0) v2 = -1e9f;
                    Cf[off] = v2;
                }
            }
            __syncwarp();
        }
    }
}

// ---------------- tf32 GEMM (fp32 in/out, fp32 accum) for the FFN ----------------
// EPI: 1 = +bias, ReLU, store f32 | 2 = +residual +bias, store f32
template<int EPI>
__global__ void __launch_bounds__(256) eb_gemm32_kernel(
    const float* __restrict__ A, int lda,
    const float* __restrict__ Bm, int ldb,
    float* __restrict__ C, int ldc,
    const float* __restrict__ bias,
    const float* __restrict__ resid,
    int K)
{
    constexpr int BM = 128, BN = 128, BK = 16;
    constexpr int WARPS_N = 4, WM = 64;       // 2x4 warps, each 64x32
    constexpr int FM = 4;

    __shared__ float As[BM][BK + 4];
    __shared__ float Bs[BK][BN + 4];
    __shared__ float epi[8][16 * 20];

    int m0 = blockIdx.y * BM;
    int n0 = blockIdx.x * BN;
    int tid = threadIdx.x;
    int w = tid >> 5, lane = tid & 31;
    int wm = w / WARPS_N, wn = w % WARPS_N;

    wmma::fragment<wmma::accumulator, 16, 16, 8, float> acc[FM][2];
    #pragma unroll
    for (int i = 0; i < FM; i++)
        #pragma unroll
        for (int j = 0; j < 2; j++) wmma::fill_fragment(acc[i][j], 0.f);

    for (int k0 = 0; k0 < K; k0 += BK) {
        // A tile 128x16 f32 = 512 float4
        #pragma unroll
        for (int i = 0; i < 2; i++) {
            int vi = tid + i * 256;
            int r = vi >> 2, c = (vi & 3) * 4;
            *(float4*)&As[r][c] = *(const float4*)&A[(size_t)(m0 + r) * lda + k0 + c];
        }
        // B tile 16x128 f32 = 512 float4
        #pragma unroll
        for (int i = 0; i < 2; i++) {
            int vi = tid + i * 256;
            int r = vi >> 5, c = (vi & 31) * 4;
            *(float4*)&Bs[r][c] = *(const float4*)&Bm[(size_t)(k0 + r) * ldb + n0 + c];
        }
        __syncthreads();
        #pragma unroll
        for (int kk = 0; kk < BK; kk += 8) {
            wmma::fragment<wmma::matrix_a, 16, 16, 8, wmma::precision::tf32, wmma::row_major> af[FM];
            wmma::fragment<wmma::matrix_b, 16, 16, 8, wmma::precision::tf32, wmma::row_major> bfr[2];
            #pragma unroll
            for (int i = 0; i < FM; i++) {
                wmma::load_matrix_sync(af[i], &As[wm * WM + i * 16][kk], BK + 4);
                #pragma unroll
                for (int t = 0; t < af[i].num_elements; t++)
                    af[i].x[t] = wmma::__float_to_tf32(af[i].x[t]);
            }
            #pragma unroll
            for (int j = 0; j < 2; j++) {
                wmma::load_matrix_sync(bfr[j], &Bs[kk][wn * 32 + j * 16], BN + 4);
                #pragma unroll
                for (int t = 0; t < bfr[j].num_elements; t++)
                    bfr[j].x[t] = wmma::__float_to_tf32(bfr[j].x[t]);
            }
            #pragma unroll
            for (int i = 0; i < FM; i++)
                #pragma unroll
                for (int j = 0; j < 2; j++)
                    wmma::mma_sync(acc[i][j], af[i], bfr[j], acc[i][j]);
        }
        __syncthreads();
    }

    #pragma unroll
    for (int i = 0; i < FM; i++) {
        #pragma unroll
        for (int j = 0; j < 2; j++) {
            wmma::store_matrix_sync(&epi[w][0], acc[i][j], 20, wmma::mem_row_major);
            __syncwarp();
            int gr0 = m0 + wm * WM + i * 16;
            int gc0 = n0 + wn * 32 + j * 16;
            #pragma unroll
            for (int e = 0; e < 8; e++) {
                int ei = lane + e * 32;
                int rr = ei >> 4, cc = ei & 15;
                float v2 = epi[w][rr * 20 + cc];
                int gr = gr0 + rr, gc = gc0 + cc;
                size_t off = (size_t)gr * ldc + gc;
                if (EPI == 1) {
                    v2 += bias[gc];
                    C[off] = fmaxf(v2, 0.f);
                } else {
                    C[off] = v2 + resid[off] + bias[gc];
                }
            }
            __syncwarp();
        }
    }
}

// ---------------- launch ----------------
extern "C" void kernel_launch(void* const* d_in, const int* in_sizes, int n_in,
                              void* d_out, int out_size) {
    const float* x    = (const float*)d_in[0];
    const int*   mask = (const int*)  d_in[1];
    const float* wq   = (const float*)d_in[2];
    const float* wk   = (const float*)d_in[3];
    const float* wv   = (const float*)d_in[4];
    const float* wo   = (const float*)d_in[5];
    const float* w1   = (const float*)d_in[6];
    const float* b1   = (const float*)d_in[7];
    const float* w2   = (const float*)d_in[8];
    const float* b2   = (const float*)d_in[9];
    const float* ln1a = (const float*)d_in[10];
    const float* ln1b = (const float*)d_in[11];
    const float* ln2a = (const float*)d_in[12];
    const float* ln2b = (const float*)d_in[13];
    float* out = (float*)d_out;

    bf16 *p_wqkv, *p_wo, *p_xn, *p_qkv, *p_q, *p_kT, *p_v, *p_attn, *p_ctx, *p_ctxr;
    float *p_scores, *p_xnf, *p_ff1f;
    cudaGetSymbolAddress((void**)&p_wqkv,  g_wqkv);
    cudaGetSymbolAddress((void**)&p_wo,    g_wo);
    cudaGetSymbolAddress((void**)&p_xn,    g_xn);
    cudaGetSymbolAddress((void**)&p_qkv,   g_qkv);
    cudaGetSymbolAddress((void**)&p_q,     g_q);
    cudaGetSymbolAddress((void**)&p_kT,    g_kT);
    cudaGetSymbolAddress((void**)&p_v,     g_v);
    cudaGetSymbolAddress((void**)&p_scores,g_scores);
    cudaGetSymbolAddress((void**)&p_attn,  g_attn);
    cudaGetSymbolAddress((void**)&p_ctx,   g_ctx);
    cudaGetSymbolAddress((void**)&p_ctxr,  g_ctxr);
    cudaGetSymbolAddress((void**)&p_xnf,   g_xnf);
    cudaGetSymbolAddress((void**)&p_ff1f,  g_ff1f);

    // weight conversion (attention weights only)
    eb_pack_wqkv<<<(D_*3*D_ + 255)/256, 256>>>(wq, wk, wv);
    eb_cast_kernel<<<(D_*D_/4 + 255)/256, 256>>>((const float4*)wo, (__nv_bfloat162*)p_wo, D_*D_/4);

    // LN1 -> bf16
    eb_ln_kernel<bf16><<<T_, 256>>>(x, ln1a, ln1b, p_xn);

    // fused QKV projection: [4096,1024] @ [1024,3072] -> bf16
    eb_gemm_kernel<128, 0><<<dim3(3*D_/128, T_/128, 1), 256>>>(
        p_xn, 0, D_, p_wqkv, 0, 3*D_, p_qkv, 0, 3*D_,
        nullptr, nullptr, D_, 0.f);
    eb_reshape_qkv<<<(T_*3*D_ + 255)/256, 256>>>();

    // scores = q @ kT / sqrt(DK) + mask  (batched over 32 heads, K=64)
    eb_gemm_kernel<128, 3><<<dim3(S_/128, S_/128, BH_), 256>>>(
        p_q, (size_t)S_*DK_, DK_, p_kT, (size_t)DK_*S_, S_, p_scores, (size_t)S_*S_, S_,
        nullptr, mask, DK_, 0.125f);

    eb_softmax_kernel<<<BH_*S_, 256>>>();

    // ctx = attn @ v  (batched, N=64, K=2048)
    eb_gemm_kernel<64, 0><<<dim3(1, S_/128, BH_), 256>>>(
        p_attn, (size_t)S_*S_, S_, p_v, (size_t)S_*DK_, DK_, p_ctx, (size_t)S_*DK_, DK_,
        nullptr, nullptr, S_, 0.f);
    eb_reshape_ctx<<<(T_*D_ + 255)/256, 256>>>();

    // x1 = x + ctx @ wo  (fp32, into d_out)
    eb_gemm_kernel<128, 2><<<dim3(D_/128, T_/128, 1), 256>>>(
        p_ctxr, 0, D_, p_wo, 0, D_, out, 0, D_,
        x, nullptr, D_, 0.f);

    // LN2 -> fp32
    eb_ln_kernel<float><<<T_, 256>>>(out, ln2a, ln2b, p_xnf);

    // ff1 = relu(xn2 @ w1 + b1) -> fp32 (tf32 tensor cores)
    eb_gemm32_kernel<1><<<dim3(DFF_/128, T_/128, 1), 256>>>(
        p_xnf, D_, w1, DFF_, p_ff1f, DFF_, b1, nullptr, D_);

    // out = x1 + ff1 @ w2 + b2  (fp32, in-place on d_out)
    eb_gemm32_kernel<2><<<dim3(D_/128, T_/128, 1), 256>>>(
        p_ff1f, DFF_, w2, D_, out, D_, b2, out, DFF_);
}

// round 6
// speedup vs baseline: 1.3848x; 1.3848x over previous
#include <cuda_runtime.h>
#include <cuda_bf16.h>
#include <mma.h>
#include <cstdint>

using namespace nvcuda;
typedef __nv_bfloat16 bf16;

#define B_   2
#define S_   2048
#define D_   1024
#define H_   16
#define DK_  64
#define DFF_ 4096
#define T_   (B_*S_)    // 4096 tokens
#define BH_  (B_*H_)    // 32 batched heads

// ---------------- scratch (device globals; no allocation allowed) ----------------
__device__ bf16  g_wqkv[D_*3*D_];
__device__ bf16  g_wo  [D_*D_];
__device__ bf16  g_xn  [T_*D_];
__device__ bf16  g_qkv [T_*3*D_];
__device__ bf16  g_ctxr[T_*D_];
__device__ float g_xnf [T_*D_];                 // fp32 LN2 output
__device__ float g_ff1f[(size_t)T_*DFF_];       // fp32 FFN hidden (64 MB)

// ---------------- async copy helpers ----------------
__device__ __forceinline__ uint32_t smem_u32(const void* p) {
    return (uint32_t)__cvta_generic_to_shared(p);
}
#define CP16(dst_u32, src_ptr) \
    asm volatile("cp.async.ca.shared.global [%0], [%1], 16;" :: "r"(dst_u32), "l"(src_ptr))
#define CP_COMMIT() asm volatile("cp.async.commit_group;")
#define CP_WAIT0()  asm volatile("cp.async.wait_group 0;")
#define CP_WAIT1()  asm volatile("cp.async.wait_group 1;")

#define LDMX4(R0,R1,R2,R3,ADDR) \
    asm volatile("ldmatrix.sync.aligned.m8n8.x4.shared.b16 {%0,%1,%2,%3}, [%4];" \
        : "=r"(R0),"=r"(R1),"=r"(R2),"=r"(R3) : "r"(ADDR))
#define LDMX4T(R0,R1,R2,R3,ADDR) \
    asm volatile("ldmatrix.sync.aligned.m8n8.x4.trans.shared.b16 {%0,%1,%2,%3}, [%4];" \
        : "=r"(R0),"=r"(R1),"=r"(R2),"=r"(R3) : "r"(ADDR))
#define MMA16816(D, A0,A1,A2,A3, B0,B1) \
    asm volatile("mma.sync.aligned.m16n8k16.row.col.f32.bf16.bf16.f32 " \
        "{%0,%1,%2,%3}, {%4,%5,%6,%7}, {%8,%9}, {%0,%1,%2,%3};" \
        : "+f"(D[0]), "+f"(D[1]), "+f"(D[2]), "+f"(D[3]) \
        : "r"(A0), "r"(A1), "r"(A2), "r"(A3), "r"(B0), "r"(B1))

__device__ __forceinline__ uint32_t pack_bf16(float x, float y) {
    __nv_bfloat162 t = __floats2bfloat162_rn(x, y);
    return *(uint32_t*)&t;
}

// ---------------- small utility kernels ----------------
__global__ void eb_cast_kernel(const float4* __restrict__ src, __nv_bfloat162* __restrict__ dst, int n4) {
    int i = blockIdx.x * blockDim.x + threadIdx.x;
    if (i < n4) {
        float4 v = src[i];
        dst[2*i]   = __floats2bfloat162_rn(v.x, v.y);
        dst[2*i+1] = __floats2bfloat162_rn(v.z, v.w);
    }
}

__global__ void eb_pack_wqkv(const float* __restrict__ wq, const float* __restrict__ wk,
                             const float* __restrict__ wv) {
    int i = blockIdx.x * 256 + threadIdx.x;
    if (i >= D_*3*D_) return;
    int k = i / (3*D_), n = i % (3*D_);
    const float* src = (n < D_) ? wq : ((n < 2*D_) ? wk : wv);
    g_wqkv[i] = __float2bfloat16(src[k*D_ + (n & (D_-1))]);
}

// ---------------- LayerNorm (TF-style: eps added to std) ----------------
template<typename OT>
__global__ void eb_ln_kernel(const float* __restrict__ x, const float* __restrict__ ga,
                             const float* __restrict__ gb, OT* __restrict__ out) {
    __shared__ float red[2][8];
    int row = blockIdx.x, tid = threadIdx.x;
    const float4* xr = (const float4*)(x + (size_t)row * D_);
    float4 v = xr[tid];
    float s = v.x + v.y + v.z + v.w;
    #pragma unroll
    for (int o = 16; o; o >>= 1) s += __shfl_xor_sync(0xffffffffu, s, o);
    if ((tid & 31) == 0) red[0][tid >> 5] = s;
    __syncthreads();
    float mean = 0.f;
    #pragma unroll
    for (int i = 0; i < 8; i++) mean += red[0][i];
    mean *= (1.0f / D_);
    float d0 = v.x - mean, d1 = v.y - mean, d2 = v.z - mean, d3 = v.w - mean;
    float q = d0*d0 + d1*d1 + d2*d2 + d3*d3;
    #pragma unroll
    for (int o = 16; o; o >>= 1) q += __shfl_xor_sync(0xffffffffu, q, o);
    if ((tid & 31) == 0) red[1][tid >> 5] = q;
    __syncthreads();
    float var = 0.f;
    #pragma unroll
    for (int i = 0; i < 8; i++) var += red[1][i];
    var *= (1.0f / D_);
    float inv = 1.f / (sqrtf(var) + 1e-6f);
    int c = tid * 4;
    float4 a4 = *(const float4*)(ga + c);
    float4 b4 = *(const float4*)(gb + c);
    float o0 = a4.x * d0 * inv + b4.x;
    float o1 = a4.y * d1 * inv + b4.y;
    float o2 = a4.z * d2 * inv + b4.z;
    float o3 = a4.w * d3 * inv + b4.w;
    if constexpr (sizeof(OT) == 2) {
        __nv_bfloat162* op = (__nv_bfloat162*)((bf16*)out + (size_t)row * D_ + c);
        op[0] = __floats2bfloat162_rn(o0, o1);
        op[1] = __floats2bfloat162_rn(o2, o3);
    } else {
        float4* op = (float4*)((float*)out + (size_t)row * D_ + c);
        *op = make_float4(o0, o1, o2, o3);
    }
}

// ---------------- fused flash attention ----------------
// Per block: 128 q-rows of one (b,h). 8 warps x 16 rows. Online softmax.
// Reads g_qkv [T][3*D] (q at col h*64, k at D+h*64, v at 2D+h*64).
// Writes g_ctxr [T][D] at col h*64.
__global__ void __launch_bounds__(256) eb_flash_kernel(const int* __restrict__ mask) {
    constexpr int KS = 72;               // padded row stride (bf16 elems): conflict-free ldmatrix
    constexpr int NT = S_ / 64;          // 32 kv tiles
    __shared__ __align__(16) bf16 sK[2][64*KS];
    __shared__ __align__(16) bf16 sV[2][64*KS];
    __shared__ float sMadd[S_];

    int tid = threadIdx.x, w = tid >> 5, lane = tid & 31;
    int b = blockIdx.y >> 4, h = blockIdx.y & 15;
    int q0 = blockIdx.x * 128;
    const int RS = 3*D_;

    for (int j = tid; j < S_; j += 256)
        sMadd[j] = mask[b*S_ + j] ? 0.f : -1e9f;

    // --- Q fragments (held in registers for the whole kernel) ---
    int qr = q0 + w*16 + (lane >> 2);
    int cq = (lane & 3) * 2;
    const bf16* qb = g_qkv + (size_t)(b*S_)*RS + h*64;
    uint32_t qa[4][4];
    #pragma unroll
    for (int c = 0; c < 4; c++) {
        int kk = c*16 + cq;
        qa[c][0] = *(const uint32_t*)(qb + (size_t)qr*RS + kk);
        qa[c][1] = *(const uint32_t*)(qb + (size_t)(qr+8)*RS + kk);
        qa[c][2] = *(const uint32_t*)(qb + (size_t)qr*RS + kk + 8);
        qa[c][3] = *(const uint32_t*)(qb + (size_t)(qr+8)*RS + kk + 8);
    }

    float o[8][4];
    #pragma unroll
    for (int i = 0; i < 8; i++)
        #pragma unroll
        for (int j = 0; j < 4; j++) o[i][j] = 0.f;
    float mr0 = -1e30f, mr1 = -1e30f, l0 = 0.f, l1 = 0.f;

    const bf16* kb = g_qkv + (size_t)(b*S_)*RS + D_   + h*64;
    const bf16* vb = g_qkv + (size_t)(b*S_)*RS + 2*D_ + h*64;

    // cooperative tile load mapping: 512 16B-vectors per tile, 2 per thread
    int lr = tid >> 3, lc = (tid & 7) * 8;

    // ldmatrix lane addressing
    int rK = (lane & 7) + ((lane & 16) >> 1);   // K (non-trans): tiles (n,k),(n,k+8),(n+8,k),(n+8,k+8)
    int cK = (lane & 8);
    int rV = (lane & 7) + (lane & 8);           // V (trans): tiles (k,n),(k+8,n),(k,n+8),(k+8,n+8)
    int cV = (lane & 16) >> 1;

    // prefetch tile 0
    #pragma unroll
    for (int i = 0; i < 2; i++) {
        int r = lr + i*32;
        CP16(smem_u32(&sK[0][r*KS + lc]), kb + (size_t)r*RS + lc);
        CP16(smem_u32(&sV[0][r*KS + lc]), vb + (size_t)r*RS + lc);
    }
    CP_COMMIT();

    for (int it = 0; it < NT; ++it) {
        if (it + 1 < NT) {
            int kv = (it+1)*64, bn = (it+1) & 1;
            #pragma unroll
            for (int i = 0; i < 2; i++) {
                int r = lr + i*32;
                CP16(smem_u32(&sK[bn][r*KS + lc]), kb + (size_t)(kv + r)*RS + lc);
                CP16(smem_u32(&sV[bn][r*KS + lc]), vb + (size_t)(kv + r)*RS + lc);
            }
            CP_COMMIT();
            CP_WAIT1();
        } else {
            CP_WAIT0();
        }
        __syncthreads();

        int buf = it & 1;
        int kv0 = it * 64;

        // --- S = Q @ K^T (16 x 64 per warp) ---
        float s[8][4];
        #pragma unroll
        for (int i = 0; i < 8; i++)
            #pragma unroll
            for (int j = 0; j < 4; j++) s[i][j] = 0.f;
        #pragma unroll
        for (int c = 0; c < 4; c++) {
            int kk = c*16;
            #pragma unroll
            for (int g = 0; g < 4; g++) {
                int n0 = g*16;
                uint32_t b0,b1,b2,b3;
                LDMX4(b0,b1,b2,b3, smem_u32(&sK[buf][(n0 + rK)*KS + kk + cK]));
                MMA16816(s[2*g],   qa[c][0],qa[c][1],qa[c][2],qa[c][3], b0, b1);
                MMA16816(s[2*g+1], qa[c][0],qa[c][1],qa[c][2],qa[c][3], b2, b3);
            }
        }

        // --- online softmax (rows qrow and qrow+8; cols spread over quad) ---
        float tm0 = -1e30f, tm1 = -1e30f;
        #pragma unroll
        for (int nb = 0; nb < 8; nb++) {
            float ma = sMadd[kv0 + nb*8 + cq];
            float mb = sMadd[kv0 + nb*8 + cq + 1];
            s[nb][0] = s[nb][0]*0.125f + ma;
            s[nb][1] = s[nb][1]*0.125f + mb;
            s[nb][2] = s[nb][2]*0.125f + ma;
            s[nb][3] = s[nb][3]*0.125f + mb;
            tm0 = fmaxf(tm0, fmaxf(s[nb][0], s[nb][1]));
            tm1 = fmaxf(tm1, fmaxf(s[nb][2], s[nb][3]));
        }
        tm0 = fmaxf(tm0, __shfl_xor_sync(0xffffffffu, tm0, 1));
        tm0 = fmaxf(tm0, __shfl_xor_sync(0xffffffffu, tm0, 2));
        tm1 = fmaxf(tm1, __shfl_xor_sync(0xffffffffu, tm1, 1));
        tm1 = fmaxf(tm1, __shfl_xor_sync(0xffffffffu, tm1, 2));
        float mn0 = fmaxf(mr0, tm0), mn1 = fmaxf(mr1, tm1);
        float al0 = __expf(mr0 - mn0), al1 = __expf(mr1 - mn1);
        mr0 = mn0; mr1 = mn1;
        float sum0 = 0.f, sum1 = 0.f;
        #pragma unroll
        for (int nb = 0; nb < 8; nb++) {
            s[nb][0] = __expf(s[nb][0] - mn0);
            s[nb][1] = __expf(s[nb][1] - mn0);
            s[nb][2] = __expf(s[nb][2] - mn1);
            s[nb][3] = __expf(s[nb][3] - mn1);
            sum0 += s[nb][0] + s[nb][1];
            sum1 += s[nb][2] + s[nb][3];
        }
        sum0 += __shfl_xor_sync(0xffffffffu, sum0, 1);
        sum0 += __shfl_xor_sync(0xffffffffu, sum0, 2);
        sum1 += __shfl_xor_sync(0xffffffffu, sum1, 1);
        sum1 += __shfl_xor_sync(0xffffffffu, sum1, 2);
        l0 = l0*al0 + sum0;
        l1 = l1*al1 + sum1;
        #pragma unroll
        for (int nb = 0; nb < 8; nb++) {
            o[nb][0] *= al0; o[nb][1] *= al0;
            o[nb][2] *= al1; o[nb][3] *= al1;
        }

        // --- P fragments (bf16) ---
        uint32_t pa[4][4];
        #pragma unroll
        for (int c = 0; c < 4; c++) {
            pa[c][0] = pack_bf16(s[2*c][0],   s[2*c][1]);
            pa[c][1] = pack_bf16(s[2*c][2],   s[2*c][3]);
            pa[c][2] = pack_bf16(s[2*c+1][0], s[2*c+1][1]);
            pa[c][3] = pack_bf16(s[2*c+1][2], s[2*c+1][3]);
        }

        // --- O += P @ V ---
        #pragma unroll
        for (int c = 0; c < 4; c++) {
            int kk = c*16;
            #pragma unroll
            for (int g = 0; g < 4; g++) {
                int n0 = g*16;
                uint32_t v0,v1,v2,v3;
                LDMX4T(v0,v1,v2,v3, smem_u32(&sV[buf][(kk + rV)*KS + n0 + cV]));
                MMA16816(o[2*g],   pa[c][0],pa[c][1],pa[c][2],pa[c][3], v0, v1);
                MMA16816(o[2*g+1], pa[c][0],pa[c][1],pa[c][2],pa[c][3], v2, v3);
            }
        }
        __syncthreads();
    }

    // --- write ctx ---
    float inv0 = 1.f / l0, inv1 = 1.f / l1;
    bf16* ob = g_ctxr + (size_t)(b*S_)*D_ + h*64;
    int orow = q0 + w*16 + (lane >> 2);
    #pragma unroll
    for (int nb = 0; nb < 8; nb++) {
        int col = nb*8 + cq;
        *(uint32_t*)(ob + (size_t)orow*D_ + col)     = pack_bf16(o[nb][0]*inv0, o[nb][1]*inv0);
        *(uint32_t*)(ob + (size_t)(orow+8)*D_ + col) = pack_bf16(o[nb][2]*inv1, o[nb][3]*inv1);
    }
}

// ---------------- bf16 wmma GEMM, cp.async double-buffered ----------------
// C[M,N] = A[M,K] @ B[K,N]. EPI: 0 = store bf16 | 2 = +residual, store f32
template<int EPI>
__global__ void __launch_bounds__(256) eb_gemm_kernel(
    const bf16* __restrict__ A, int lda,
    const bf16* __restrict__ Bm, int ldb,
    void* __restrict__ Cout, int ldc,
    const float* __restrict__ resid, int K)
{
    constexpr int BM = 128, BN = 128, BK = 32;
    __shared__ __align__(16) bf16 As[2][BM][BK + 8];
    __shared__ __align__(16) bf16 Bs[2][BK][BN + 8];
    __shared__ float epi[8][16 * 20];

    int m0 = blockIdx.y * BM, n0 = blockIdx.x * BN;
    int tid = threadIdx.x;
    int w = tid >> 5, lane = tid & 31;
    int wm = w >> 2, wn = w & 3;              // 2 x 4 warps, each 64x32

    int ar = tid >> 2, ac = (tid & 3) * 8;    // A: rows ar, ar+64
    int br = tid >> 4, bc = (tid & 15) * 8;   // B: rows br, br+16

    wmma::fragment<wmma::accumulator, 16, 16, 16, float> acc[4][2];
    #pragma unroll
    for (int i = 0; i < 4; i++)
        #pragma unroll
        for (int j = 0; j < 2; j++) wmma::fill_fragment(acc[i][j], 0.f);

    // stage 0
    CP16(smem_u32(&As[0][ar][ac]),    A  + (size_t)(m0 + ar)*lda + ac);
    CP16(smem_u32(&As[0][ar+64][ac]), A  + (size_t)(m0 + ar + 64)*lda + ac);
    CP16(smem_u32(&Bs[0][br][bc]),    Bm + (size_t)br*ldb + n0 + bc);
    CP16(smem_u32(&Bs[0][br+16][bc]), Bm + (size_t)(br + 16)*ldb + n0 + bc);
    CP_COMMIT();

    int NIT = K / BK;
    for (int itk = 0; itk < NIT; ++itk) {
        if (itk + 1 < NIT) {
            int k0 = (itk + 1) * BK, sn = (itk + 1) & 1;
            CP16(smem_u32(&As[sn][ar][ac]),    A  + (size_t)(m0 + ar)*lda + k0 + ac);
            CP16(smem_u32(&As[sn][ar+64][ac]), A  + (size_t)(m0 + ar + 64)*lda + k0 + ac);
            CP16(smem_u32(&Bs[sn][br][bc]),    Bm + (size_t)(k0 + br)*ldb + n0 + bc);
            CP16(smem_u32(&Bs[sn][br+16][bc]), Bm + (size_t)(k0 + br + 16)*ldb + n0 + bc);
            CP_COMMIT();
            CP_WAIT1();
        } else {
            CP_WAIT0();
        }
        __syncthreads();
        int st = itk & 1;
        #pragma unroll
        for (int kk = 0; kk < BK; kk += 16) {
            wmma::fragment<wmma::matrix_a, 16, 16, 16, bf16, wmma::row_major> af[4];
            wmma::fragment<wmma::matrix_b, 16, 16, 16, bf16, wmma::row_major> bfr[2];
            #pragma unroll
            for (int i = 0; i < 4; i++)
                wmma::load_matrix_sync(af[i], &As[st][wm * 64 + i * 16][kk], BK + 8);
            #pragma unroll
            for (int j = 0; j < 2; j++)
                wmma::load_matrix_sync(bfr[j], &Bs[st][kk][wn * 32 + j * 16], BN + 8);
            #pragma unroll
            for (int i = 0; i < 4; i++)
                #pragma unroll
                for (int j = 0; j < 2; j++)
                    wmma::mma_sync(acc[i][j], af[i], bfr[j], acc[i][j]);
        }
        __syncthreads();
    }

    float* Cf = (float*)Cout;
    bf16*  Cb = (bf16*)Cout;
    #pragma unroll
    for (int i = 0; i < 4; i++) {
        #pragma unroll
        for (int j = 0; j < 2; j++) {
            wmma::store_matrix_sync(&epi[w][0], acc[i][j], 20, wmma::mem_row_major);
            __syncwarp();
            int gr0 = m0 + wm * 64 + i * 16;
            int gc0 = n0 + wn * 32 + j * 16;
            #pragma unroll
            for (int e = 0; e < 8; e++) {
                int ei = lane + e * 32;
                int rr = ei >> 4, cc = ei & 15;
                float v2 = epi[w][rr * 20 + cc];
                size_t off = (size_t)(gr0 + rr) * ldc + gc0 + cc;
                if (EPI == 0) Cb[off] = __float2bfloat16(v2);
                else          Cf[off] = v2 + resid[off];
            }
            __syncwarp();
        }
    }
}

// ---------------- tf32 GEMM (fp32 in/out), cp.async double-buffered ----------------
// EPI: 1 = +bias, ReLU, store f32 | 2 = +residual +bias, store f32
template<int EPI>
__global__ void __launch_bounds__(256) eb_gemm32_kernel(
    const float* __restrict__ A, int lda,
    const float* __restrict__ Bm, int ldb,
    float* __restrict__ C, int ldc,
    const float* __restrict__ bias,
    const float* __restrict__ resid,
    int K)
{
    constexpr int BM = 128, BN = 128, BK = 16;
    __shared__ __align__(16) float As[2][BM][BK + 4];
    __shared__ __align__(16) float Bs[2][BK][BN + 4];
    __shared__ float epi[8][16 * 20];

    int m0 = blockIdx.y * BM, n0 = blockIdx.x * BN;
    int tid = threadIdx.x;
    int w = tid >> 5, lane = tid & 31;
    int wm = w >> 2, wn = w & 3;

    int ar = tid >> 2, ac = (tid & 3) * 4;    // A: rows ar, ar+64
    int br = tid >> 5, bc = (tid & 31) * 4;   // B: rows br, br+8

    wmma::fragment<wmma::accumulator, 16, 16, 8, float> acc[4][2];
    #pragma unroll
    for (int i = 0; i < 4; i++)
        #pragma unroll
        for (int j = 0; j < 2; j++) wmma::fill_fragment(acc[i][j], 0.f);

    CP16(smem_u32(&As[0][ar][ac]),    A  + (size_t)(m0 + ar)*lda + ac);
    CP16(smem_u32(&As[0][ar+64][ac]), A  + (size_t)(m0 + ar + 64)*lda + ac);
    CP16(smem_u32(&Bs[0][br][bc]),    Bm + (size_t)br*ldb + n0 + bc);
    CP16(smem_u32(&Bs[0][br+8][bc]),  Bm + (size_t)(br + 8)*ldb + n0 + bc);
    CP_COMMIT();

    int NIT = K / BK;
    for (int itk = 0; itk < NIT; ++itk) {
        if (itk + 1 < NIT) {
            int k0 = (itk + 1) * BK, sn = (itk + 1) & 1;
            CP16(smem_u32(&As[sn][ar][ac]),    A  + (size_t)(m0 + ar)*lda + k0 + ac);
            CP16(smem_u32(&As[sn][ar+64][ac]), A  + (size_t)(m0 + ar + 64)*lda + k0 + ac);
            CP16(smem_u32(&Bs[sn][br][bc]),    Bm + (size_t)(k0 + br)*ldb + n0 + bc);
            CP16(smem_u32(&Bs[sn][br+8][bc]),  Bm + (size_t)(k0 + br + 8)*ldb + n0 + bc);
            CP_COMMIT();
            CP_WAIT1();
        } else {
            CP_WAIT0();
        }
        __syncthreads();
        int st = itk & 1;
        #pragma unroll
        for (int kk = 0; kk < BK; kk += 8) {
            wmma::fragment<wmma::matrix_a, 16, 16, 8, wmma::precision::tf32, wmma::row_major> af[4];
            wmma::fragment<wmma::matrix_b, 16, 16, 8, wmma::precision::tf32, wmma::row_major> bfr[2];
            #pragma unroll
            for (int i = 0; i < 4; i++) {
                wmma::load_matrix_sync(af[i], &As[st][wm * 64 + i * 16][kk], BK + 4);
                #pragma unroll
                for (int t = 0; t < af[i].num_elements; t++)
                    af[i].x[t] = wmma::__float_to_tf32(af[i].x[t]);
            }
            #pragma unroll
            for (int j = 0; j < 2; j++) {
                wmma::load_matrix_sync(bfr[j], &Bs[st][kk][wn * 32 + j * 16], BN + 4);
                #pragma unroll
                for (int t = 0; t < bfr[j].num_elements; t++)
                    bfr[j].x[t] = wmma::__float_to_tf32(bfr[j].x[t]);
            }
            #pragma unroll
            for (int i = 0; i < 4; i++)
                #pragma unroll
                for (int j = 0; j < 2; j++)
                    wmma::mma_sync(acc[i][j], af[i], bfr[j], acc[i][j]);
        }
        __syncthreads();
    }

    #pragma unroll
    for (int i = 0; i < 4; i++) {
        #pragma unroll
        for (int j = 0; j < 2; j++) {
            wmma::store_matrix_sync(&epi[w][0], acc[i][j], 20, wmma::mem_row_major);
            __syncwarp();
            int gr0 = m0 + wm * 64 + i * 16;
            int gc0 = n0 + wn * 32 + j * 16;
            #pragma unroll
            for (int e = 0; e < 8; e++) {
                int ei = lane + e * 32;
                int rr = ei >> 4, cc = ei & 15;
                float v2 = epi[w][rr * 20 + cc];
                int gc = gc0 + cc;
                size_t off = (size_t)(gr0 + rr) * ldc + gc;
                if (EPI == 1) C[off] = fmaxf(v2 + bias[gc], 0.f);
                else          C[off] = v2 + resid[off] + bias[gc];
            }
            __syncwarp();
        }
    }
}

// ---------------- launch ----------------
extern "C" void kernel_launch(void* const* d_in, const int* in_sizes, int n_in,
                              void* d_out, int out_size) {
    const float* x    = (const float*)d_in[0];
    const int*   mask = (const int*)  d_in[1];
    const float* wq   = (const float*)d_in[2];
    const float* wk   = (const float*)d_in[3];
    const float* wv   = (const float*)d_in[4];
    const float* wo   = (const float*)d_in[5];
    const float* w1   = (const float*)d_in[6];
    const float* b1   = (const float*)d_in[7];
    const float* w2   = (const float*)d_in[8];
    const float* b2   = (const float*)d_in[9];
    const float* ln1a = (const float*)d_in[10];
    const float* ln1b = (const float*)d_in[11];
    const float* ln2a = (const float*)d_in[12];
    const float* ln2b = (const float*)d_in[13];
    float* out = (float*)d_out;

    bf16 *p_wqkv, *p_wo, *p_xn, *p_qkv, *p_ctxr;
    float *p_xnf, *p_ff1f;
    cudaGetSymbolAddress((void**)&p_wqkv,  g_wqkv);
    cudaGetSymbolAddress((void**)&p_wo,    g_wo);
    cudaGetSymbolAddress((void**)&p_xn,    g_xn);
    cudaGetSymbolAddress((void**)&p_qkv,   g_qkv);
    cudaGetSymbolAddress((void**)&p_ctxr,  g_ctxr);
    cudaGetSymbolAddress((void**)&p_xnf,   g_xnf);
    cudaGetSymbolAddress((void**)&p_ff1f,  g_ff1f);

    // attention weights -> bf16
    eb_pack_wqkv<<<(D_*3*D_ + 255)/256, 256>>>(wq, wk, wv);
    eb_cast_kernel<<<(D_*D_/4 + 255)/256, 256>>>((const float4*)wo, (__nv_bfloat162*)p_wo, D_*D_/4);

    // LN1 -> bf16
    eb_ln_kernel<bf16><<<T_, 256>>>(x, ln1a, ln1b, p_xn);

    // fused QKV projection: [4096,1024] @ [1024,3072] -> g_qkv bf16
    eb_gemm_kernel<0><<<dim3(3*D_/128, T_/128), 256>>>(
        p_xn, D_, p_wqkv, 3*D_, p_qkv, 3*D_, nullptr, D_);

    // fused flash attention -> g_ctxr [T][D] bf16
    eb_flash_kernel<<<dim3(S_/128, BH_), 256>>>(mask);

    // x1 = x + ctx @ wo  (fp32, into d_out)
    eb_gemm_kernel<2><<<dim3(D_/128, T_/128), 256>>>(
        p_ctxr, D_, p_wo, D_, out, D_, x, D_);

    // LN2 -> fp32
    eb_ln_kernel<float><<<T_, 256>>>(out, ln2a, ln2b, p_xnf);

    // ff1 = relu(xn2 @ w1 + b1) -> fp32 (tf32 tensor cores)
    eb_gemm32_kernel<1><<<dim3(DFF_/128, T_/128), 256>>>(
        p_xnf, D_, w1, DFF_, p_ff1f, DFF_, b1, nullptr, D_);

    // out = x1 + ff1 @ w2 + b2  (fp32, in-place on d_out)
    eb_gemm32_kernel<2><<<dim3(D_/128, T_/128), 256>>>(
        p_ff1f, DFF_, w2, D_, out, D_, b2, out, DFF_);
}

// round 9
// speedup vs baseline: 3.5110x; 2.5354x over previous
#include <cuda_runtime.h>
#include <cuda_fp16.h>
#include <mma.h>
#include <cstdint>

using namespace nvcuda;
typedef __half fp16;

#define B_   2
#define S_   2048
#define D_   1024
#define H_   16
#define DK_  64
#define DFF_ 4096
#define T_   (B_*S_)    // 4096 tokens
#define BH_  (B_*H_)    // 32 batched heads

// ---------------- scratch (device globals; no allocation allowed) ----------------
__device__ fp16  g_wqkv[D_*3*D_];
__device__ fp16  g_wo  [D_*D_];
__device__ fp16  g_w1  [D_*DFF_];
__device__ fp16  g_w2  [DFF_*D_];
__device__ fp16  g_xn  [T_*D_];                 // LN1 then LN2 output
__device__ fp16  g_qkv [T_*3*D_];
__device__ fp16  g_ctxr[T_*D_];
__device__ fp16  g_ff1 [(size_t)T_*DFF_];       // fp16 FFN hidden (32 MB)

// ---------------- async copy helpers ----------------
__device__ __forceinline__ uint32_t smem_u32(const void* p) {
    return (uint32_t)__cvta_generic_to_shared(p);
}
#define CP16(dst_u32, src_ptr) \
    asm volatile("cp.async.ca.shared.global [%0], [%1], 16;" :: "r"(dst_u32), "l"(src_ptr))
#define CP_COMMIT() asm volatile("cp.async.commit_group;")
#define CP_WAIT0()  asm volatile("cp.async.wait_group 0;")
#define CP_WAIT1()  asm volatile("cp.async.wait_group 1;")

#define LDMX4(R0,R1,R2,R3,ADDR) \
    asm volatile("ldmatrix.sync.aligned.m8n8.x4.shared.b16 {%0,%1,%2,%3}, [%4];" \
        : "=r"(R0),"=r"(R1),"=r"(R2),"=r"(R3) : "r"(ADDR))
#define LDMX4T(R0,R1,R2,R3,ADDR) \
    asm volatile("ldmatrix.sync.aligned.m8n8.x4.trans.shared.b16 {%0,%1,%2,%3}, [%4];" \
        : "=r"(R0),"=r"(R1),"=r"(R2),"=r"(R3) : "r"(ADDR))
#define MMA16816(D, A0,A1,A2,A3, B0,B1) \
    asm volatile("mma.sync.aligned.m16n8k16.row.col.f32.f16.f16.f32 " \
        "{%0,%1,%2,%3}, {%4,%5,%6,%7}, {%8,%9}, {%0,%1,%2,%3};" \
        : "+f"(D[0]), "+f"(D[1]), "+f"(D[2]), "+f"(D[3]) \
        : "r"(A0), "r"(A1), "r"(A2), "r"(A3), "r"(B0), "r"(B1))

__device__ __forceinline__ uint32_t pack_f16(float x, float y) {
    __half2 t = __floats2half2_rn(x, y);
    return *(uint32_t*)&t;
}

// ---------------- small utility kernels ----------------
__global__ void eb_cast_kernel(const float4* __restrict__ src, __half2* __restrict__ dst, int n4) {
    int i = blockIdx.x * blockDim.x + threadIdx.x;
    if (i < n4) {
        float4 v = src[i];
        dst[2*i]   = __floats2half2_rn(v.x, v.y);
        dst[2*i+1] = __floats2half2_rn(v.z, v.w);
    }
}

__global__ void eb_pack_wqkv(const float* __restrict__ wq, const float* __restrict__ wk,
                             const float* __restrict__ wv) {
    int i = blockIdx.x * 256 + threadIdx.x;
    if (i >= D_*3*D_) return;
    int k = i / (3*D_), n = i % (3*D_);
    const float* src = (n < D_) ? wq : ((n < 2*D_) ? wk : wv);
    g_wqkv[i] = __float2half_rn(src[k*D_ + (n & (D_-1))]);
}

// ---------------- LayerNorm (TF-style: eps added to std) -> fp16 ----------------
__global__ void eb_ln_kernel(const float* __restrict__ x, const float* __restrict__ ga,
                             const float* __restrict__ gb, fp16* __restrict__ out) {
    __shared__ float red[2][8];
    int row = blockIdx.x, tid = threadIdx.x;
    const float4* xr = (const float4*)(x + (size_t)row * D_);
    float4 v = xr[tid];
    float s = v.x + v.y + v.z + v.w;
    #pragma unroll
    for (int o = 16; o; o >>= 1) s += __shfl_xor_sync(0xffffffffu, s, o);
    if ((tid & 31) == 0) red[0][tid >> 5] = s;
    __syncthreads();
    float mean = 0.f;
    #pragma unroll
    for (int i = 0; i < 8; i++) mean += red[0][i];
    mean *= (1.0f / D_);
    float d0 = v.x - mean, d1 = v.y - mean, d2 = v.z - mean, d3 = v.w - mean;
    float q = d0*d0 + d1*d1 + d2*d2 + d3*d3;
    #pragma unroll
    for (int o = 16; o; o >>= 1) q += __shfl_xor_sync(0xffffffffu, q, o);
    if ((tid & 31) == 0) red[1][tid >> 5] = q;
    __syncthreads();
    float var = 0.f;
    #pragma unroll
    for (int i = 0; i < 8; i++) var += red[1][i];
    var *= (1.0f / D_);
    float inv = 1.f / (sqrtf(var) + 1e-6f);
    int c = tid * 4;
    float4 a4 = *(const float4*)(ga + c);
    float4 b4 = *(const float4*)(gb + c);
    __half2* op = (__half2*)(out + (size_t)row * D_ + c);
    op[0] = __floats2half2_rn(a4.x * d0 * inv + b4.x, a4.y * d1 * inv + b4.y);
    op[1] = __floats2half2_rn(a4.z * d2 * inv + b4.z, a4.w * d3 * inv + b4.w);
}

// ---------------- fused flash attention ----------------
// Per block: 128 q-rows of one (b,h). 8 warps x 16 rows. Online softmax.
// Reads g_qkv [T][3*D] (q at col h*64, k at D+h*64, v at 2D+h*64).
// Writes g_ctxr [T][D] at col h*64.
__global__ void __launch_bounds__(256) eb_flash_kernel(const int* __restrict__ mask) {
    constexpr int KS = 72;               // padded row stride: conflict-free ldmatrix
    constexpr int NT = S_ / 64;          // 32 kv tiles
    __shared__ __align__(16) fp16 sK[2][64*KS];
    __shared__ __align__(16) fp16 sV[2][64*KS];
    __shared__ float sMadd[S_];

    int tid = threadIdx.x, w = tid >> 5, lane = tid & 31;
    int b = blockIdx.y >> 4, h = blockIdx.y & 15;
    int q0 = blockIdx.x * 128;
    const int RS = 3*D_;

    for (int j = tid; j < S_; j += 256)
        sMadd[j] = mask[b*S_ + j] ? 0.f : -1e9f;

    // --- Q fragments (held in registers for the whole kernel) ---
    int qr = q0 + w*16 + (lane >> 2);
    int cq = (lane & 3) * 2;
    const fp16* qb = g_qkv + (size_t)(b*S_)*RS + h*64;
    uint32_t qa[4][4];
    #pragma unroll
    for (int c = 0; c < 4; c++) {
        int kk = c*16 + cq;
        qa[c][0] = *(const uint32_t*)(qb + (size_t)qr*RS + kk);
        qa[c][1] = *(const uint32_t*)(qb + (size_t)(qr+8)*RS + kk);
        qa[c][2] = *(const uint32_t*)(qb + (size_t)qr*RS + kk + 8);
        qa[c][3] = *(const uint32_t*)(qb + (size_t)(qr+8)*RS + kk + 8);
    }

    float o[8][4];
    #pragma unroll
    for (int i = 0; i < 8; i++)
        #pragma unroll
        for (int j = 0; j < 4; j++) o[i][j] = 0.f;
    float mr0 = -1e30f, mr1 = -1e30f, l0 = 0.f, l1 = 0.f;

    const fp16* kb = g_qkv + (size_t)(b*S_)*RS + D_   + h*64;
    const fp16* vb = g_qkv + (size_t)(b*S_)*RS + 2*D_ + h*64;

    // cooperative tile load mapping: 512 16B-vectors per tile, 2 per thread
    int lr = tid >> 3, lc = (tid & 7) * 8;

    // ldmatrix lane addressing
    int rK = (lane & 7) + ((lane & 16) >> 1);
    int cK = (lane & 8);
    int rV = (lane & 7) + (lane & 8);
    int cV = (lane & 16) >> 1;

    // prefetch tile 0
    #pragma unroll
    for (int i = 0; i < 2; i++) {
        int r = lr + i*32;
        CP16(smem_u32(&sK[0][r*KS + lc]), kb + (size_t)r*RS + lc);
        CP16(smem_u32(&sV[0][r*KS + lc]), vb + (size_t)r*RS + lc);
    }
    CP_COMMIT();

    for (int it = 0; it < NT; ++it) {
        if (it + 1 < NT) {
            int kv = (it+1)*64, bn = (it+1) & 1;
            #pragma unroll
            for (int i = 0; i < 2; i++) {
                int r = lr + i*32;
                CP16(smem_u32(&sK[bn][r*KS + lc]), kb + (size_t)(kv + r)*RS + lc);
                CP16(smem_u32(&sV[bn][r*KS + lc]), vb + (size_t)(kv + r)*RS + lc);
            }
            CP_COMMIT();
            CP_WAIT1();
        } else {
            CP_WAIT0();
        }
        __syncthreads();

        int buf = it & 1;
        int kv0 = it * 64;

        // --- S = Q @ K^T (16 x 64 per warp) ---
        float s[8][4];
        #pragma unroll
        for (int i = 0; i < 8; i++)
            #pragma unroll
            for (int j = 0; j < 4; j++) s[i][j] = 0.f;
        #pragma unroll
        for (int c = 0; c < 4; c++) {
            int kk = c*16;
            #pragma unroll
            for (int g = 0; g < 4; g++) {
                int n0 = g*16;
                uint32_t b0,b1,b2,b3;
                LDMX4(b0,b1,b2,b3, smem_u32(&sK[buf][(n0 + rK)*KS + kk + cK]));
                MMA16816(s[2*g],   qa[c][0],qa[c][1],qa[c][2],qa[c][3], b0, b1);
                MMA16816(s[2*g+1], qa[c][0],qa[c][1],qa[c][2],qa[c][3], b2, b3);
            }
        }

        // --- online softmax ---
        float tm0 = -1e30f, tm1 = -1e30f;
        #pragma unroll
        for (int nb = 0; nb < 8; nb++) {
            float ma = sMadd[kv0 + nb*8 + cq];
            float mb = sMadd[kv0 + nb*8 + cq + 1];
            s[nb][0] = s[nb][0]*0.125f + ma;
            s[nb][1] = s[nb][1]*0.125f + mb;
            s[nb][2] = s[nb][2]*0.125f + ma;
            s[nb][3] = s[nb][3]*0.125f + mb;
            tm0 = fmaxf(tm0, fmaxf(s[nb][0], s[nb][1]));
            tm1 = fmaxf(tm1, fmaxf(s[nb][2], s[nb][3]));
        }
        tm0 = fmaxf(tm0, __shfl_xor_sync(0xffffffffu, tm0, 1));
        tm0 = fmaxf(tm0, __shfl_xor_sync(0xffffffffu, tm0, 2));
        tm1 = fmaxf(tm1, __shfl_xor_sync(0xffffffffu, tm1, 1));
        tm1 = fmaxf(tm1, __shfl_xor_sync(0xffffffffu, tm1, 2));
        float mn0 = fmaxf(mr0, tm0), mn1 = fmaxf(mr1, tm1);
        float al0 = __expf(mr0 - mn0), al1 = __expf(mr1 - mn1);
        mr0 = mn0; mr1 = mn1;
        float sum0 = 0.f, sum1 = 0.f;
        #pragma unroll
        for (int nb = 0; nb < 8; nb++) {
            s[nb][0] = __expf(s[nb][0] - mn0);
            s[nb][1] = __expf(s[nb][1] - mn0);
            s[nb][2] = __expf(s[nb][2] - mn1);
            s[nb][3] = __expf(s[nb][3] - mn1);
            sum0 += s[nb][0] + s[nb][1];
            sum1 += s[nb][2] + s[nb][3];
        }
        sum0 += __shfl_xor_sync(0xffffffffu, sum0, 1);
        sum0 += __shfl_xor_sync(0xffffffffu, sum0, 2);
        sum1 += __shfl_xor_sync(0xffffffffu, sum1, 1);
        sum1 += __shfl_xor_sync(0xffffffffu, sum1, 2);
        l0 = l0*al0 + sum0;
        l1 = l1*al1 + sum1;
        #pragma unroll
        for (int nb = 0; nb < 8; nb++) {
            o[nb][0] *= al0; o[nb][1] *= al0;
            o[nb][2] *= al1; o[nb][3] *= al1;
        }

        // --- P fragments (fp16) ---
        uint32_t pa[4][4];
        #pragma unroll
        for (int c = 0; c < 4; c++) {
            pa[c][0] = pack_f16(s[2*c][0],   s[2*c][1]);
            pa[c][1] = pack_f16(s[2*c][2],   s[2*c][3]);
            pa[c][2] = pack_f16(s[2*c+1][0], s[2*c+1][1]);
            pa[c][3] = pack_f16(s[2*c+1][2], s[2*c+1][3]);
        }

        // --- O += P @ V ---
        #pragma unroll
        for (int c = 0; c < 4; c++) {
            int kk = c*16;
            #pragma unroll
            for (int g = 0; g < 4; g++) {
                int n0 = g*16;
                uint32_t v0,v1,v2,v3;
                LDMX4T(v0,v1,v2,v3, smem_u32(&sV[buf][(kk + rV)*KS + n0 + cV]));
                MMA16816(o[2*g],   pa[c][0],pa[c][1],pa[c][2],pa[c][3], v0, v1);
                MMA16816(o[2*g+1], pa[c][0],pa[c][1],pa[c][2],pa[c][3], v2, v3);
            }
        }
        __syncthreads();
    }

    // --- write ctx ---
    float inv0 = 1.f / l0, inv1 = 1.f / l1;
    fp16* ob = g_ctxr + (size_t)(b*S_)*D_ + h*64;
    int orow = q0 + w*16 + (lane >> 2);
    #pragma unroll
    for (int nb = 0; nb < 8; nb++) {
        int col = nb*8 + cq;
        *(uint32_t*)(ob + (size_t)orow*D_ + col)     = pack_f16(o[nb][0]*inv0, o[nb][1]*inv0);
        *(uint32_t*)(ob + (size_t)(orow+8)*D_ + col) = pack_f16(o[nb][2]*inv1, o[nb][3]*inv1);
    }
}

// ---------------- fp16 wmma GEMM, cp.async double-buffered ----------------
// C[M,N] = A[M,K] @ B[K,N].
// EPI: 0 = store fp16 | 1 = +bias, ReLU, store fp16 | 2 = +residual, store f32
//      3 = +residual +bias, store f32
template<int EPI>
__global__ void __launch_bounds__(256) eb_gemm_kernel(
    const fp16* __restrict__ A, int lda,
    const fp16* __restrict__ Bm, int ldb,
    void* __restrict__ Cout, int ldc,
    const float* __restrict__ bias,
    const float* __restrict__ resid, int K)
{
    constexpr int BM = 128, BN = 128, BK = 32;
    __shared__ __align__(16) fp16 As[2][BM][BK + 8];
    __shared__ __align__(16) fp16 Bs[2][BK][BN + 8];
    __shared__ float epi[8][16 * 20];

    int m0 = blockIdx.y * BM, n0 = blockIdx.x * BN;
    int tid = threadIdx.x;
    int w = tid >> 5, lane = tid & 31;
    int wm = w >> 2, wn = w & 3;              // 2 x 4 warps, each 64x32

    int ar = tid >> 2, ac = (tid & 3) * 8;    // A: rows ar, ar+64
    int br = tid >> 4, bc = (tid & 15) * 8;   // B: rows br, br+16

    wmma::fragment<wmma::accumulator, 16, 16, 16, float> acc[4][2];
    #pragma unroll
    for (int i = 0; i < 4; i++)
        #pragma unroll
        for (int j = 0; j < 2; j++) wmma::fill_fragment(acc[i][j], 0.f);

    // stage 0
    CP16(smem_u32(&As[0][ar][ac]),    A  + (size_t)(m0 + ar)*lda + ac);
    CP16(smem_u32(&As[0][ar+64][ac]), A  + (size_t)(m0 + ar + 64)*lda + ac);
    CP16(smem_u32(&Bs[0][br][bc]),    Bm + (size_t)br*ldb + n0 + bc);
    CP16(smem_u32(&Bs[0][br+16][bc]), Bm + (size_t)(br + 16)*ldb + n0 + bc);
    CP_COMMIT();

    int NIT = K / BK;
    for (int itk = 0; itk < NIT; ++itk) {
        if (itk + 1 < NIT) {
            int k0 = (itk + 1) * BK, sn = (itk + 1) & 1;
            CP16(smem_u32(&As[sn][ar][ac]),    A  + (size_t)(m0 + ar)*lda + k0 + ac);
            CP16(smem_u32(&As[sn][ar+64][ac]), A  + (size_t)(m0 + ar + 64)*lda + k0 + ac);
            CP16(smem_u32(&Bs[sn][br][bc]),    Bm + (size_t)(k0 + br)*ldb + n0 + bc);
            CP16(smem_u32(&Bs[sn][br+16][bc]), Bm + (size_t)(k0 + br + 16)*ldb + n0 + bc);
            CP_COMMIT();
            CP_WAIT1();
        } else {
            CP_WAIT0();
        }
        __syncthreads();
        int st = itk & 1;
        #pragma unroll
        for (int kk = 0; kk < BK; kk += 16) {
            wmma::fragment<wmma::matrix_a, 16, 16, 16, __half, wmma::row_major> af[4];
            wmma::fragment<wmma::matrix_b, 16, 16, 16, __half, wmma::row_major> bfr[2];
            #pragma unroll
            for (int i = 0; i < 4; i++)
                wmma::load_matrix_sync(af[i], &As[st][wm * 64 + i * 16][kk], BK + 8);
            #pragma unroll
            for (int j = 0; j < 2; j++)
                wmma::load_matrix_sync(bfr[j], &Bs[st][kk][wn * 32 + j * 16], BN + 8);
            #pragma unroll
            for (int i = 0; i < 4; i++)
                #pragma unroll
                for (int j = 0; j < 2; j++)
                    wmma::mma_sync(acc[i][j], af[i], bfr[j], acc[i][j]);
        }
        __syncthreads();
    }

    float* Cf = (float*)Cout;
    fp16*  Cb = (fp16*)Cout;
    #pragma unroll
    for (int i = 0; i < 4; i++) {
        #pragma unroll
        for (int j = 0; j < 2; j++) {
            wmma::store_matrix_sync(&epi[w][0], acc[i][j], 20, wmma::mem_row_major);
            __syncwarp();
            int gr0 = m0 + wm * 64 + i * 16;
            int gc0 = n0 + wn * 32 + j * 16;
            #pragma unroll
            for (int e = 0; e < 8; e++) {
                int ei = lane + e * 32;
                int rr = ei >> 4, cc = ei & 15;
                float v2 = epi[w][rr * 20 + cc];
                int gc = gc0 + cc;
                size_t off = (size_t)(gr0 + rr) * ldc + gc;
                if (EPI == 0)      Cb[off] = __float2half_rn(v2);
                else if (EPI == 1) Cb[off] = __float2half_rn(fmaxf(v2 + bias[gc], 0.f));
                else if (EPI == 2) Cf[off] = v2 + resid[off];
                else               Cf[off] = v2 + resid[off] + bias[gc];
            }
            __syncwarp();
        }
    }
}

// ---------------- launch ----------------
extern "C" void kernel_launch(void* const* d_in, const int* in_sizes, int n_in,
                              void* d_out, int out_size) {
    const float* x    = (const float*)d_in[0];
    const int*   mask = (const int*)  d_in[1];
    const float* wq   = (const float*)d_in[2];
    const float* wk   = (const float*)d_in[3];
    const float* wv   = (const float*)d_in[4];
    const float* wo   = (const float*)d_in[5];
    const float* w1   = (const float*)d_in[6];
    const float* b1   = (const float*)d_in[7];
    const float* w2   = (const float*)d_in[8];
    const float* b2   = (const float*)d_in[9];
    const float* ln1a = (const float*)d_in[10];
    const float* ln1b = (const float*)d_in[11];
    const float* ln2a = (const float*)d_in[12];
    const float* ln2b = (const float*)d_in[13];
    float* out = (float*)d_out;

    fp16 *p_wqkv, *p_wo, *p_w1, *p_w2, *p_xn, *p_qkv, *p_ctxr, *p_ff1;
    cudaGetSymbolAddress((void**)&p_wqkv,  g_wqkv);
    cudaGetSymbolAddress((void**)&p_wo,    g_wo);
    cudaGetSymbolAddress((void**)&p_w1,    g_w1);
    cudaGetSymbolAddress((void**)&p_w2,    g_w2);
    cudaGetSymbolAddress((void**)&p_xn,    g_xn);
    cudaGetSymbolAddress((void**)&p_qkv,   g_qkv);
    cudaGetSymbolAddress((void**)&p_ctxr,  g_ctxr);
    cudaGetSymbolAddress((void**)&p_ff1,   g_ff1);

    // weights -> fp16
    eb_pack_wqkv<<<(D_*3*D_ + 255)/256, 256>>>(wq, wk, wv);
    eb_cast_kernel<<<(D_*D_/4 + 255)/256, 256>>>((const float4*)wo, (__half2*)p_wo, D_*D_/4);
    eb_cast_kernel<<<(D_*DFF_/4 + 255)/256, 256>>>((const float4*)w1, (__half2*)p_w1, D_*DFF_/4);
    eb_cast_kernel<<<(DFF_*D_/4 + 255)/256, 256>>>((const float4*)w2, (__half2*)p_w2, DFF_*D_/4);

    // LN1 -> fp16
    eb_ln_kernel<<<T_, 256>>>(x, ln1a, ln1b, p_xn);

    // fused QKV projection: [4096,1024] @ [1024,3072] -> g_qkv fp16
    eb_gemm_kernel<0><<<dim3(3*D_/128, T_/128), 256>>>(
        p_xn, D_, p_wqkv, 3*D_, p_qkv, 3*D_, nullptr, nullptr, D_);

    // fused flash attention -> g_ctxr [T][D] fp16
    eb_flash_kernel<<<dim3(S_/128, BH_), 256>>>(mask);

    // x1 = x + ctx @ wo  (fp32, into d_out)
    eb_gemm_kernel<2><<<dim3(D_/128, T_/128), 256>>>(
        p_ctxr, D_, p_wo, D_, out, D_, nullptr, x, D_);

    // LN2 -> fp16 (g_xn is free after the QKV GEMM)
    eb_ln_kernel<<<T_, 256>>>(out, ln2a, ln2b, p_xn);

    // ff1 = relu(xn2 @ w1 + b1) -> fp16
    eb_gemm_kernel<1><<<dim3(DFF_/128, T_/128), 256>>>(
        p_xn, D_, p_w1, DFF_, p_ff1, DFF_, b1, nullptr, D_);

    // out = x1 + ff1 @ w2 + b2  (fp32, in-place on d_out)
    eb_gemm_kernel<3><<<dim3(D_/128, T_/128), 256>>>(
        p_ff1, DFF_, p_w2, D_, out, D_, b2, out, DFF_);
}